// round 17
// baseline (speedup 1.0000x reference)
#include <cuda_runtime.h>
#include <cuda_fp16.h>

// ============================================================================
// 2-layer LSTM (B=256, T=512, I=64, H=512) + head on sm_100 base via
// mma.sync.m16n8k16 fp16, 2-term A split (exact to 2^-24), B single fp16,
// fp32 accum. 128 persistent CTAs x 256 thr, merged phases.
// R16: A-residency re-tile. CTA = 32 gate rows x 128 batch (m-split 64,
// n-split 2): per-CTA A = 205KB; smem cut to ONE 16KB reduce buffer so the
// L1 carveout (~212KB) holds all of A -> the 51MB/phase A stream from L2
// disappears after warmup. Warps: 2 K-groups x 4 n-slots, tile m32 x n32.
// K-group reduce in-place in smem (grp0 stores, grp1 adds). Barriers: 2
// independent 64-CTA n-groups + one global before the head.
// ============================================================================

typedef unsigned u32;

#define NCTA 128
#define NTHR 256
#define NQ0  36     // layer-0 k16 tiles: 32 (h0) + 4 (x)
#define NQ1  64     // layer-1 k16 tiles: 32 (h0 cur) + 32 (h1 prev)
#define SMEM_DYN (4096 * 4)    // one 32x128 fp32 reduce buffer = 16KB

// ---------------- device scratch (static) -----------------------------------
__device__ __align__(16) __half g_WP0[128 * NQ0 * 512];
__device__ __align__(16) __half g_WP1[128 * NQ1 * 512];
__device__ __align__(16) __half g_XP[512 * 4 * 16 * 256];
__device__ __align__(16) __half g_HB[2 * 2 * 32 * 16 * 256];
__device__ float g_C[2 * 512 * 256];
__device__ float g_h1fin[512 * 256];
__device__ float g_bias[2 * 2048];
__device__ u32 g_barCnt[3];
__device__ volatile u32 g_barGen[3];

// ---------------- helpers ---------------------------------------------------
// Barrier over `cnt` CTAs using slot `idx` (0-1: n-groups of 64; 2: global).
__device__ __forceinline__ void group_barrier(int idx, u32 cnt) {
    __syncthreads();
    if (threadIdx.x == 0) {
        u32 gen = g_barGen[idx];
        __threadfence();
        if (atomicAdd(&g_barCnt[idx], 1u) == cnt - 1u) {
            g_barCnt[idx] = 0u;
            __threadfence();
            g_barGen[idx] = gen + 1u;
        } else {
            while (g_barGen[idx] == gen) { }
        }
        __threadfence();
    }
    __syncthreads();
}

__device__ __forceinline__ float sigm(float x) { return 1.0f / (1.0f + expf(-x)); }

__device__ __forceinline__ void mma4(float* d, uint4 a, u32 b0, u32 b1) {
    asm volatile(
        "mma.sync.aligned.m16n8k16.row.col.f32.f16.f16.f32 "
        "{%0,%1,%2,%3}, {%4,%5,%6,%7}, {%8,%9}, {%0,%1,%2,%3};"
        : "+f"(d[0]), "+f"(d[1]), "+f"(d[2]), "+f"(d[3])
        : "r"(a.x), "r"(a.y), "r"(a.z), "r"(a.w), "r"(b0), "r"(b1));
}

// One contiguous K segment of NQ k16-steps for an m32 x n32 warp tile.
// A0p/A1p: lane-adjusted A block ptrs for the two m16 tiles (+64 uint4/q;
// expected L1-resident). Bp: lane-adjusted B ptr; the warp's two n16
// blocks are Bp and Bp+32 (+512 uint4 per q). 2-term x 2m x 4n8 = 16 HMMA,
// 6 LDG.128 per q.
template <int NQ>
__device__ __forceinline__ void gemm_seg(
    const uint4* __restrict__ A0p, const uint4* __restrict__ A1p,
    const uint4* __restrict__ Bp, float acc[2][4][4])
{
#pragma unroll 4
    for (int q = 0; q < NQ; q++) {
        uint4 b0  = __ldcg(Bp);
        uint4 b1  = __ldcg(Bp + 32);
        uint4 ah0 = __ldg(A0p);  uint4 al0 = __ldg(A0p + 1);
        uint4 ah1 = __ldg(A1p);  uint4 al1 = __ldg(A1p + 1);
        mma4(acc[0][0], ah0, b0.x, b0.y);
        mma4(acc[0][0], al0, b0.x, b0.y);
        mma4(acc[0][1], ah0, b0.z, b0.w);
        mma4(acc[0][1], al0, b0.z, b0.w);
        mma4(acc[0][2], ah0, b1.x, b1.y);
        mma4(acc[0][2], al0, b1.x, b1.y);
        mma4(acc[0][3], ah0, b1.z, b1.w);
        mma4(acc[0][3], al0, b1.z, b1.w);
        mma4(acc[1][0], ah1, b0.x, b0.y);
        mma4(acc[1][0], al1, b0.x, b0.y);
        mma4(acc[1][1], ah1, b0.z, b0.w);
        mma4(acc[1][1], al1, b0.z, b0.w);
        mma4(acc[1][2], ah1, b1.x, b1.y);
        mma4(acc[1][2], al1, b1.x, b1.y);
        mma4(acc[1][3], ah1, b1.z, b1.w);
        mma4(acc[1][3], al1, b1.z, b1.w);
        A0p += 64; A1p += 64; Bp += 512;
    }
}

// Store / add one warp's partial D tile (m32 x n32) into the 32x128 buffer.
__device__ __forceinline__ void store_partials(
    float acc[2][4][4], float* buf, int wn, int lane)
{
#pragma unroll
    for (int mi = 0; mi < 2; mi++)
#pragma unroll
        for (int ni = 0; ni < 4; ni++) {
            int lr = mi * 16 + (lane >> 2);
            int cl = wn * 32 + ni * 8 + (lane & 3) * 2;
            float* d = acc[mi][ni];
            *(float2*)&buf[lr * 128 + cl]       = make_float2(d[0], d[1]);
            *(float2*)&buf[(lr + 8) * 128 + cl] = make_float2(d[2], d[3]);
        }
}

__device__ __forceinline__ void add_partials(
    float acc[2][4][4], float* buf, int wn, int lane)
{
#pragma unroll
    for (int mi = 0; mi < 2; mi++)
#pragma unroll
        for (int ni = 0; ni < 4; ni++) {
            int lr = mi * 16 + (lane >> 2);
            int cl = wn * 32 + ni * 8 + (lane & 3) * 2;
            float* d = acc[mi][ni];
            float2 t0 = *(float2*)&buf[lr * 128 + cl];
            t0.x += d[0]; t0.y += d[1];
            *(float2*)&buf[lr * 128 + cl] = t0;
            float2 t1 = *(float2*)&buf[(lr + 8) * 128 + cl];
            t1.x += d[2]; t1.y += d[3];
            *(float2*)&buf[(lr + 8) * 128 + cl] = t1;
        }
}

// Cell update for one layer from the reduced 32x128 buffer.
// CTA tile: j in [m_cta*8, +8), b in [n_cta*128, +128). 4 cells/thread.
__device__ __forceinline__ void cell_upd(
    const float* buf, int lay, int pwv, int m_cta, int n_cta,
    int tid, bool fin)
{
    float* Cp = g_C + lay * 131072;
    const float* bp = g_bias + lay * 2048;
#pragma unroll
    for (int e = 0; e < 4; e++) {
        int cell = e * NTHR + tid;          // 1024 cells
        int jl = cell >> 7, bl = cell & 127;
        int j = m_cta * 8 + jl;
        int b = n_cta * 128 + bl;
        float iv = buf[(jl * 4 + 0) * 128 + bl] + __ldg(bp + 0 * 512 + j);
        float fv = buf[(jl * 4 + 1) * 128 + bl] + __ldg(bp + 1 * 512 + j);
        float gv = buf[(jl * 4 + 2) * 128 + bl] + __ldg(bp + 2 * 512 + j);
        float ov = buf[(jl * 4 + 3) * 128 + bl] + __ldg(bp + 3 * 512 + j);
        float c = Cp[j * 256 + b];
        c = sigm(fv) * c + sigm(iv) * tanhf(gv);
        Cp[j * 256 + b] = c;
        float hv = sigm(ov) * tanhf(c);
        // fp16 B-fragment scatter (general form): block q = j>>4, kl = j&15
        int qh = j >> 4, kl = j & 15;
        int r  = kl >> 3, tg = (kl >> 1) & 3, hb = kl & 1;
        int n8 = b >> 3, nl = b & 7;
        int p  = n8 & 1, n16 = n8 >> 1;
        int l2 = nl * 4 + tg;
        int blk = ((pwv * 2 + lay) * 32 + qh) * 16 + n16;
        g_HB[blk * 256 + l2 * 8 + p * 4 + r * 2 + hb] = __float2half(hv);
        if (fin) g_h1fin[j * 256 + b] = hv;
    }
}

// ---------------- the persistent kernel -------------------------------------
extern __shared__ __align__(16) float gsm[];   // 32x128 fp32 reduce buffer

__global__ void __launch_bounds__(NTHR, 1) lstm_all(
    const float* __restrict__ x,
    const float* __restrict__ Wih0, const float* __restrict__ Whh0,
    const float* __restrict__ bih0, const float* __restrict__ bhh0,
    const float* __restrict__ Wih1, const float* __restrict__ Whh1,
    const float* __restrict__ bih1, const float* __restrict__ bhh1,
    const float* __restrict__ Wout, const float* __restrict__ bout,
    float* __restrict__ out)
{
    const int tid  = threadIdx.x;
    const int wid  = tid >> 5;
    const int lane = tid & 31;
    const int gtid = blockIdx.x * NTHR + tid;
    const int NT   = NCTA * NTHR;

    // ======== prep: identical layouts to R15 winner ========
    for (int i = gtid; i < 128 * NQ0 * 512; i += NT) {
        int bi = i >> 9, off = i & 511;
        int l = off >> 4, rem = off & 15;
        int sect = rem >> 3, r = (rem >> 1) & 3, h = rem & 1;
        int mt = bi / NQ0, q = bi % NQ0;
        int lr = (l >> 2) + (r & 1) * 8;
        int c  = (l & 3) * 2 + h + (r >> 1) * 8;
        int R  = mt * 16 + lr;
        int GR = (R & 3) * 512 + (R >> 2);
        int k  = q * 16 + c;
        float w = (k < 512) ? Whh0[GR * 512 + k] : Wih0[GR * 64 + (k - 512)];
        __half hh = __float2half(w);
        g_WP0[i] = sect ? __float2half(w - __half2float(hh)) : hh;
    }
    for (int i = gtid; i < 128 * NQ1 * 512; i += NT) {
        int bi = i >> 9, off = i & 511;
        int l = off >> 4, rem = off & 15;
        int sect = rem >> 3, r = (rem >> 1) & 3, h = rem & 1;
        int mt = bi / NQ1, q = bi % NQ1;
        int lr = (l >> 2) + (r & 1) * 8;
        int c  = (l & 3) * 2 + h + (r >> 1) * 8;
        int R  = mt * 16 + lr;
        int GR = (R & 3) * 512 + (R >> 2);
        int k  = q * 16 + c;
        float w = (k < 512) ? Wih1[GR * 512 + k] : Whh1[GR * 512 + (k - 512)];
        __half hh = __float2half(w);
        g_WP1[i] = sect ? __float2half(w - __half2float(hh)) : hh;
    }
    for (int i = gtid; i < 512 * 4 * 16 * 256; i += NT) {
        int bi = i >> 8, off = i & 255;
        int l = off >> 3, rem = off & 7;
        int p = rem >> 2, r = (rem >> 1) & 1, h = rem & 1;
        int n16 = bi & 15, rest = bi >> 4;
        int qp = rest & 3, t = rest >> 2;
        int n8 = n16 * 2 + p;
        int b  = n8 * 8 + (l >> 2);
        int kk = r * 8 + (l & 3) * 2 + h;
        int ii = qp * 16 + kk;
        g_XP[i] = __float2half(x[(b * 512 + t) * 64 + ii]);
    }
    for (int i = gtid; i < 2 * 2 * 32 * 16 * 256; i += NT)
        g_HB[i] = __float2half(0.f);
    for (int i = gtid; i < 2 * 512 * 256; i += NT) g_C[i] = 0.f;
    for (int i = gtid; i < 2048; i += NT) {
        g_bias[i]        = bih0[i] + bhh0[i];
        g_bias[2048 + i] = bih1[i] + bhh1[i];
    }

    group_barrier(2, NCTA);   // global: prep visible everywhere

    // ======== merged mainloop: phase t = { L1(t-1), L0(t) } ========
    const int m_cta = blockIdx.x >> 1;     // 64 m-tiles: j in [m_cta*8, +8)
    const int n_cta = blockIdx.x & 1;      // 2 n-tiles:  b in [n_cta*128, +128)
    const int grp = wid >> 2;              // K-half group
    const int wn  = wid & 3;               // n32 slot
    const int mt0 = m_cta * 2;             // CTA's two m16 tiles
    const int n16b = n_cta * 8 + wn * 2;   // warp's two n16 blocks

    const uint4* WP0v = (const uint4*)g_WP0;
    const uint4* WP1v = (const uint4*)g_WP1;
    const uint4* XPv  = (const uint4*)g_XP;
    const uint4* HBv  = (const uint4*)g_HB;

    for (int t = 0; t <= 512; t++) {
        const int u = t & 1, v = u ^ 1;
        const bool do1 = (t >= 1);
        const bool do0 = (t <= 511);

        if (do1) {
            // L1(t-1): q0-31 = h0(t-1)@(v,0), q32-63 = h1(t-2)@(u,1)
            float acc[2][4][4] = {};
            const uint4* A0 = WP1v + (mt0 * NQ1) * 64 + lane * 2;
            const uint4* A1 = WP1v + ((mt0 + 1) * NQ1) * 64 + lane * 2;
            if (grp == 0) {
                gemm_seg<32>(A0, A1,
                             HBv + (((v * 2 + 0) * 32) * 16 + n16b) * 32 + lane, acc);
            } else {
                gemm_seg<32>(A0 + 32 * 64, A1 + 32 * 64,
                             HBv + (((u * 2 + 1) * 32) * 16 + n16b) * 32 + lane, acc);
            }
            // in-place K-group reduce in the single 16KB buffer
            if (grp == 0) store_partials(acc, gsm, wn, lane);
            __syncthreads();
            if (grp == 1) add_partials(acc, gsm, wn, lane);
            __syncthreads();
            cell_upd(gsm, 1, v, m_cta, n_cta, tid, t == 512);
        }
        if (do0) {
            // L0(t): q0-31 = h0(t-1)@(v,0), q32-35 = x(t)
            float acc[2][4][4] = {};
            const uint4* A0 = WP0v + (mt0 * NQ0) * 64 + lane * 2;
            const uint4* A1 = WP0v + ((mt0 + 1) * NQ0) * 64 + lane * 2;
            const uint4* Bh = HBv + (((v * 2 + 0) * 32) * 16 + n16b) * 32 + lane;
            if (grp == 0) {
                gemm_seg<18>(A0, A1, Bh, acc);
            } else {
                gemm_seg<14>(A0 + 18 * 64, A1 + 18 * 64, Bh + 18 * 512, acc);
                gemm_seg<4>(A0 + 32 * 64, A1 + 32 * 64,
                            XPv + ((t * 4) * 16 + n16b) * 32 + lane, acc);
            }
            __syncthreads();   // L1 cell_upd reads of buf complete
            if (grp == 0) store_partials(acc, gsm, wn, lane);
            __syncthreads();
            if (grp == 1) add_partials(acc, gsm, wn, lane);
            __syncthreads();
            cell_upd(gsm, 0, u, m_cta, n_cta, tid, false);
        }

        // all h/C exchange stays within this n-group of 64 CTAs
        group_barrier(n_cta, 64);
    }

    group_barrier(2, NCTA);   // global: h1fin complete before head

    // ======== head ========
    if (blockIdx.x == 0) {
        int b = tid;
        float a = __ldg(bout);
#pragma unroll 8
        for (int j = 0; j < 512; j++)
            a += fmaxf(__ldcg(g_h1fin + j * 256 + b), 0.f) * __ldg(Wout + j);
        out[b] = a;
    }
}

// ---------------- launch ----------------------------------------------------
extern "C" void kernel_launch(void* const* d_in, const int* in_sizes, int n_in,
                              void* d_out, int out_size) {
    (void)in_sizes; (void)n_in; (void)out_size;
    const float* x    = (const float*)d_in[0];
    const float* Wih0 = (const float*)d_in[1];
    const float* Whh0 = (const float*)d_in[2];
    const float* bih0 = (const float*)d_in[3];
    const float* bhh0 = (const float*)d_in[4];
    const float* Wih1 = (const float*)d_in[5];
    const float* Whh1 = (const float*)d_in[6];
    const float* bih1 = (const float*)d_in[7];
    const float* bhh1 = (const float*)d_in[8];
    const float* Wout = (const float*)d_in[9];
    const float* bout = (const float*)d_in[10];
    float* out = (float*)d_out;

    cudaFuncSetAttribute(lstm_all, cudaFuncAttributeMaxDynamicSharedMemorySize, SMEM_DYN);
    lstm_all<<<NCTA, NTHR, SMEM_DYN>>>(x, Wih0, Whh0, bih0, bhh0,
                                       Wih1, Whh1, bih1, bhh1, Wout, bout, out);
}